// round 1
// baseline (speedup 1.0000x reference)
#include <cuda_runtime.h>

// ConvSpatialPropagationNet — the reference's propagation step is pointwise:
// nws = gate_sum * d (identical coefficient as gate_sum itself), so the
// recurrence d <- (1-g)*raw + g*d with d0 = raw is a fixed point: output ==
// blur_depth exactly (up to ~5e-6 relative fp drift in the reference).
// Kernel = vectorized D2D copy of blur_depth (d_in[1]) into d_out.

__global__ void cspn_copy_kernel(const float4* __restrict__ src,
                                 float4* __restrict__ dst, int n4) {
    int i = blockIdx.x * blockDim.x + threadIdx.x;
    if (i < n4) dst[i] = src[i];
}

__global__ void cspn_copy_tail(const float* __restrict__ src,
                               float* __restrict__ dst, int start, int n) {
    int i = start + blockIdx.x * blockDim.x + threadIdx.x;
    if (i < n) dst[i] = src[i];
}

extern "C" void kernel_launch(void* const* d_in, const int* in_sizes, int n_in,
                              void* d_out, int out_size) {
    // Input order per metadata: guidance, blur_depth, sparse_depth, sum_w
    const float* blur_depth = (const float*)d_in[1];
    float* out = (float*)d_out;

    int n = out_size;            // 8*352*1216 = 3,424,256
    int n4 = n >> 2;             // 856,064 float4 (n divisible by 4)
    int threads = 256;
    int blocks = (n4 + threads - 1) / threads;

    cspn_copy_kernel<<<blocks, threads>>>(
        (const float4*)blur_depth, (float4*)out, n4);

    int rem_start = n4 << 2;
    if (rem_start < n) {
        int rem = n - rem_start;
        cspn_copy_tail<<<(rem + 255) / 256, 256>>>(blur_depth, out, rem_start, rem);
    }
}

// round 2
// speedup vs baseline: 1.3301x; 1.3301x over previous
#include <cuda_runtime.h>

// ConvSpatialPropagationNet — reference recurrence is a fixed point at
// d0 = blur_depth (gates multiply depth at the SAME padded coordinate, so
// nws == gate_sum * d and d <- (1-g)*raw + g*d stays at raw). Output is a
// pure copy of blur_depth (rel_err ~6e-8 vs reference's fp drift).
//
// R2: MLP=4 copy. Each thread front-batches 4 independent LDG.128 before
// storing, quartering exposed DRAM latency vs the R1 one-load-per-thread
// version (which ran at only 25% of HBM).

__global__ void cspn_copy4_kernel(const float4* __restrict__ src,
                                  float4* __restrict__ dst) {
    const int S = gridDim.x * blockDim.x;        // 214,016
    int i = blockIdx.x * blockDim.x + threadIdx.x;
    // n4 = 4*S exactly (checked host-side) -> no bounds checks.
    float4 a = src[i];
    float4 b = src[i + S];
    float4 c = src[i + 2 * S];
    float4 d = src[i + 3 * S];
    dst[i]         = a;
    dst[i + S]     = b;
    dst[i + 2 * S] = c;
    dst[i + 3 * S] = d;
}

// Generic fallback (grid-stride, any size) — not used for the benched shape.
__global__ void cspn_copy_gs_kernel(const float4* __restrict__ src,
                                    float4* __restrict__ dst, int n4) {
    int i = blockIdx.x * blockDim.x + threadIdx.x;
    int S = gridDim.x * blockDim.x;
    for (; i < n4; i += S) dst[i] = src[i];
}

__global__ void cspn_copy_tail(const float* __restrict__ src,
                               float* __restrict__ dst, int start, int n) {
    int i = start + blockIdx.x * blockDim.x + threadIdx.x;
    if (i < n) dst[i] = src[i];
}

extern "C" void kernel_launch(void* const* d_in, const int* in_sizes, int n_in,
                              void* d_out, int out_size) {
    // Input order per metadata: guidance, blur_depth, sparse_depth, sum_w
    const float* blur_depth = (const float*)d_in[1];
    float* out = (float*)d_out;

    const int n = out_size;          // 3,424,256 for the benched shape
    const int n4 = n >> 2;           // 856,064 float4
    const int threads = 256;
    const int per_thread = 4;
    const int chunk = threads * per_thread;      // 1024 float4 per block

    if ((n & 3) == 0 && (n4 % chunk) == 0) {
        // Fast path: exact tiling, 836 blocks for the benched shape.
        cspn_copy4_kernel<<<n4 / chunk, threads>>>(
            (const float4*)blur_depth, (float4*)out);
    } else {
        // Generic path: vector body + scalar tail.
        if (n4 > 0) {
            int blocks = (n4 + chunk - 1) / chunk;
            cspn_copy_gs_kernel<<<blocks, threads>>>(
                (const float4*)blur_depth, (float4*)out, n4);
        }
        int rem_start = n4 << 2;
        if (rem_start < n) {
            int rem = n - rem_start;
            cspn_copy_tail<<<(rem + 255) / 256, 256>>>(blur_depth, out,
                                                       rem_start, rem);
        }
    }
}